// round 7
// baseline (speedup 1.0000x reference)
#include <cuda_runtime.h>
#include <math.h>

#define B_DIM 4096
#define N_DIM 512
#define H_DIM 1024
#define NOPS  20
#define PWRK  12               // squarings -> p = 2^12 = 4096
#define PINV  (1.0f/4096.0f)

// ---------------- static device scratch (no allocations allowed) ----------------
static __device__ float g_C[H_DIM * H_DIM];                 // W^T W      (4 MB)
static __device__ float g_Asq[2][N_DIM * N_DIM];            // squaring ping-pong (2 MB)
static __device__ float g_u[(size_t)B_DIM * H_DIM];         // W^T x      (16 MB)
static __device__ float g_zbuf[2][(size_t)B_DIM * H_DIM];   // z ping-pong (32 MB)
static __device__ float g_zpbuf[2][(size_t)B_DIM * H_DIM];  // z_prev ping-pong (32 MB)
static __device__ float g_scal[8];                          // [0]=log accum s, [1]=1/tr, [3]=1/L, [4]=lam
static __device__ float g_w[16 * 24];                       // per-iter: aw[20], bw0, bw1

// ---------------- 20-op activation mixture (matches JAX semantics) ----------------
__device__ __forceinline__ float act_mix(float v, const float* aw, float lam) {
    float av  = fabsf(v);
    float e   = expf(-av);                 // exp(-|v|)
    float i1e = 1.0f / (1.0f + e);
    float sig = (v >= 0.f) ? i1e : e * i1e;            // sigmoid(v)
    float sp  = fmaxf(v, 0.f) + log1pf(e);             // softplus(v)
    float e2  = e * e;
    float tha = (1.f - e2) / (1.f + e2);               // tanh(|v|)
    float th  = (v >= 0.f) ? tha : -tha;               // tanh(v)
    float oms = 1.f - sig;                              // sigmoid(-v) = exp(-softplus(v))
    float q   = oms * oms;                              // exp(-2*softplus(v))
    float msh = (1.f - q) / (1.f + q);                  // tanh(softplus(v))
    float erv = erff(v * 0.70710678118654752f);
    float em1 = e - 1.f;                                // expm1(v) for v<0
    float elu = (v > 0.f) ? v : em1;
    float r6  = fminf(fmaxf(v + 3.f, 0.f), 6.f) * (1.f / 6.f);

    float r;
    r  = aw[0]  * ((v > lam) ? (v - lam) : ((v < -lam) ? (v + lam) : 0.f)); // softshrink
    r += aw[1]  * fmaxf(v, 0.f);                                           // relu
    r += aw[2]  * v;                                                       // identity
    r += aw[3]  * (0.5f * v * (1.f + erv));                                // gelu (exact)
    r += aw[4]  * elu;                                                     // elu
    r += aw[5]  * ((av > lam) ? v : 0.f);                                  // hardshrink
    r += aw[6]  * fminf(fmaxf(v, -1.f), 1.f);                              // hardtanh
    r += aw[7]  * (v * r6);                                                // hardswish
    r += aw[8]  * (1.0507009873554805f * ((v > 0.f) ? v : 1.6732632423543772f * em1)); // selu
    r += aw[9]  * elu;                                                     // celu(alpha=1)
    r += aw[10] * ((v >= 0.f) ? v : 0.01f * v);                            // leaky_relu
    r += aw[11] * (v - sp);                                                // log_sigmoid
    r += aw[12] * (v - th);                                                // tanhshrink
    r += aw[13] * (v / (1.f + av));                                        // softsign
    r += aw[14] * sp;                                                      // softplus
    r += aw[15] * th;                                                      // tanh
    r += aw[16] * sig;                                                     // sigmoid
    r += aw[17] * r6;                                                      // hardsigmoid
    r += aw[18] * (v * sig);                                               // silu
    r += aw[19] * (v * msh);                                               // mish
    return r;
}

// ---------------- GEMM building blocks: 128x128 tile, BK=16, 256 thr, 8x8/thr ----------------
// load [128m x 16k] from row-major [m][k] (stride ld) -> transposed s[16][128]
__device__ __forceinline__ void load_A_T(float s[16][128], const float* src,
                                         int m0, int k0, int ld, int t) {
#pragma unroll
    for (int l = 0; l < 2; ++l) {
        int fid = t + l * 256;
        int row = fid >> 2;
        int cv  = (fid & 3) * 4;
        float4 v = *(const float4*)&src[(size_t)(m0 + row) * ld + k0 + cv];
        s[cv + 0][row] = v.x; s[cv + 1][row] = v.y;
        s[cv + 2][row] = v.z; s[cv + 3][row] = v.w;
    }
}
// load [16k x 128n] direct from row-major [k][n] (stride ld) -> s[16][128]
__device__ __forceinline__ void load_B_N(float s[16][128], const float* src,
                                         int k0, int n0, int ld, int t) {
#pragma unroll
    for (int l = 0; l < 2; ++l) {
        int fid = t + l * 256;
        int row = fid >> 5;
        int cv  = (fid & 31) * 4;
        *(float4*)&s[row][cv] = *(const float4*)&src[(size_t)(k0 + row) * ld + n0 + cv];
    }
}
__device__ __forceinline__ void mma_chunk(const float (*a_s)[128], const float (*b_s)[128],
                                          int tx, int ty, float acc[8][8]) {
#pragma unroll
    for (int kk = 0; kk < 16; ++kk) {
        float ar[8], br[8];
        *(float4*)&ar[0] = *(const float4*)&a_s[kk][ty * 8];
        *(float4*)&ar[4] = *(const float4*)&a_s[kk][ty * 8 + 4];
        *(float4*)&br[0] = *(const float4*)&b_s[kk][tx * 8];
        *(float4*)&br[4] = *(const float4*)&b_s[kk][tx * 8 + 4];
#pragma unroll
        for (int i = 0; i < 8; ++i)
#pragma unroll
            for (int j = 0; j < 8; ++j)
                acc[i][j] = fmaf(ar[i], br[j], acc[i][j]);
    }
}
__device__ __forceinline__ void store_tile(float* outp, int ldo, int m0, int n0,
                                           int tx, int ty, const float acc[8][8], float scale) {
#pragma unroll
    for (int i = 0; i < 8; ++i) {
        float v[8];
#pragma unroll
        for (int j = 0; j < 8; ++j) v[j] = acc[i][j] * scale;
        size_t off = (size_t)(m0 + ty * 8 + i) * ldo + n0 + tx * 8;
        *(float4*)&outp[off]     = *(float4*)&v[0];
        *(float4*)&outp[off + 4] = *(float4*)&v[4];
    }
}

// ---------------- one-time kernels ----------------
// A = W W^T  [512x512], K=1024
__global__ __launch_bounds__(256) void k_gemm_wwT(const float* __restrict__ W) {
    __shared__ float a_s[16][128], b_s[16][128];
    int t = threadIdx.x, tx = t & 15, ty = t >> 4;
    int n0 = blockIdx.x * 128, m0 = blockIdx.y * 128;
    float acc[8][8] = {};
    for (int k0 = 0; k0 < H_DIM; k0 += 16) {
        load_A_T(a_s, W, m0, k0, H_DIM, t);
        load_A_T(b_s, W, n0, k0, H_DIM, t);
        __syncthreads();
        mma_chunk(a_s, b_s, tx, ty, acc);
        __syncthreads();
    }
    store_tile(g_Asq[0], N_DIM, m0, n0, tx, ty, acc, 1.0f);
}
// C = W^T W  [1024x1024], K=512
__global__ __launch_bounds__(256) void k_gemm_C(const float* __restrict__ W) {
    __shared__ float a_s[16][128], b_s[16][128];
    int t = threadIdx.x, tx = t & 15, ty = t >> 4;
    int n0 = blockIdx.x * 128, m0 = blockIdx.y * 128;
    float acc[8][8] = {};
    for (int k0 = 0; k0 < N_DIM; k0 += 16) {
        load_B_N(a_s, W, k0, m0, H_DIM, t);   // Aop[m,k] = W[k,m]
        load_B_N(b_s, W, k0, n0, H_DIM, t);
        __syncthreads();
        mma_chunk(a_s, b_s, tx, ty, acc);
        __syncthreads();
    }
    store_tile(g_C, H_DIM, m0, n0, tx, ty, acc, 1.0f);
}
// u = x * W  [4096x1024], K=512
__global__ __launch_bounds__(256) void k_gemm_u(const float* __restrict__ x,
                                                const float* __restrict__ W) {
    __shared__ float a_s[16][128], b_s[16][128];
    int t = threadIdx.x, tx = t & 15, ty = t >> 4;
    int n0 = blockIdx.x * 128, m0 = blockIdx.y * 128;
    float acc[8][8] = {};
    for (int k0 = 0; k0 < N_DIM; k0 += 16) {
        load_A_T(a_s, x, m0, k0, N_DIM, t);
        load_B_N(b_s, W, k0, n0, H_DIM, t);
        __syncthreads();
        mma_chunk(a_s, b_s, tx, ty, acc);
        __syncthreads();
    }
    store_tile(g_u, H_DIM, m0, n0, tx, ty, acc, 1.0f);
}
// trace of g_Asq[sel]; update log accumulator; final -> L, 1/L, lam
__global__ void k_trace(int sel, int first, int last) {
    __shared__ float red[512];
    int t = threadIdx.x;
    red[t] = g_Asq[sel][t * N_DIM + t];
    __syncthreads();
    for (int s = 256; s > 0; s >>= 1) { if (t < s) red[t] += red[t + s]; __syncthreads(); }
    if (t == 0) {
        float tr = red[0];
        float s0 = first ? 0.f : g_scal[0];
        if (!last) {
            g_scal[0] = 2.f * (s0 + logf(tr));
            g_scal[1] = 1.f / tr;
        } else {
            float lnl = (s0 + logf(tr)) * PINV;
            float L = expf(lnl);
            g_scal[2] = L;
            g_scal[3] = 1.f / L;
            g_scal[4] = 0.001f / L;
        }
    }
}
// g_Asq[src^1] = (g_Asq[src]/tr)^2
__global__ __launch_bounds__(256) void k_gemm_square(int src) {
    __shared__ float a_s[16][128], b_s[16][128];
    int t = threadIdx.x, tx = t & 15, ty = t >> 4;
    int n0 = blockIdx.x * 128, m0 = blockIdx.y * 128;
    const float* in = g_Asq[src];
    float inv = g_scal[1];
    float acc[8][8] = {};
    for (int k0 = 0; k0 < N_DIM; k0 += 16) {
        load_A_T(a_s, in, m0, k0, N_DIM, t);
        load_B_N(b_s, in, k0, n0, N_DIM, t);
        __syncthreads();
        mma_chunk(a_s, b_s, tx, ty, acc);
        __syncthreads();
    }
    store_tile(g_Asq[src ^ 1], N_DIM, m0, n0, tx, ty, acc, inv * inv);
}
// softmax weights per iteration
__global__ void k_weights(const float* __restrict__ alpha, const float* __restrict__ beta, int T) {
    int i = threadIdx.x;
    if (i >= T) return;
    float m = -1e30f;
    for (int k = 0; k < NOPS; ++k) m = fmaxf(m, alpha[i * NOPS + k]);
    float e[NOPS], s = 0.f;
    for (int k = 0; k < NOPS; ++k) { e[k] = expf(alpha[i * NOPS + k] - m); s += e[k]; }
    float invs = 1.f / s;
    for (int k = 0; k < NOPS; ++k) g_w[i * 24 + k] = e[k] * invs;
    float b0 = beta[i * 2], b1 = beta[i * 2 + 1];
    float mb = fmaxf(b0, b1);
    float e0 = expf(b0 - mb), e1 = expf(b1 - mb);
    float ib = 1.f / (e0 + e1);
    g_w[i * 24 + 20] = e0 * ib;
    g_w[i * 24 + 21] = e1 * ib;
}
// iteration 0: z = zprev = 0 -> z_g = u/L, pure elementwise
__global__ void k_iter0(float* zext) {
    __shared__ float smw[24];
    int t = threadIdx.x;
    if (t < 22) smw[t] = g_w[t];
    __syncthreads();
    float invL = g_scal[3], lam = g_scal[4];
    float bw1 = smw[21];
    float* zo  = zext ? zext : g_zbuf[0];
    float* zpo = g_zpbuf[0];
    size_t idx = ((size_t)blockIdx.x * 256 + t) * 4;
    float4 uu = *(const float4*)&g_u[idx];
    float z0 = act_mix(uu.x * invL, smw, lam);
    float z1 = act_mix(uu.y * invL, smw, lam);
    float z2 = act_mix(uu.z * invL, smw, lam);
    float z3 = act_mix(uu.w * invL, smw, lam);
    float4 zv  = make_float4(z0, z1, z2, z3);
    float4 zpv = make_float4(bw1 * z0, bw1 * z1, bw1 * z2, bw1 * z3);
    *(float4*)&zo[idx]  = zv;
    *(float4*)&zpo[idx] = zpv;
}
// fused iteration: Cz GEMM + momentum + gradient step + 20-op mixture + beta mix
__global__ __launch_bounds__(256) void k_gemm_iter(int inSel, int outSel, float* zext,
                                                   int iter, float mom, int write_zp) {
    __shared__ float a_s[16][128], b_s[16][128];
    __shared__ float smw[24];
    int t = threadIdx.x, tx = t & 15, ty = t >> 4;
    if (t < 22) smw[t] = g_w[iter * 24 + t];
    const float* z_in  = g_zbuf[inSel];
    const float* zp_in = g_zpbuf[inSel];
    float* z_out  = zext ? zext : g_zbuf[outSel];
    float* zp_out = g_zpbuf[outSel];
    int n0 = blockIdx.x * 128, m0 = blockIdx.y * 128;
    float acc[8][8] = {};
    for (int k0 = 0; k0 < H_DIM; k0 += 16) {
#pragma unroll
        for (int l = 0; l < 2; ++l) {               // fused z_aux A-tile
            int fid = t + l * 256;
            int row = fid >> 2;
            int cv  = (fid & 3) * 4;
            size_t off = (size_t)(m0 + row) * H_DIM + k0 + cv;
            float4 a = *(const float4*)&z_in[off];
            float4 b = *(const float4*)&zp_in[off];
            a_s[cv + 0][row] = a.x + mom * (a.x - b.x);
            a_s[cv + 1][row] = a.y + mom * (a.y - b.y);
            a_s[cv + 2][row] = a.z + mom * (a.z - b.z);
            a_s[cv + 3][row] = a.w + mom * (a.w - b.w);
        }
        load_B_N(b_s, g_C, k0, n0, H_DIM, t);
        __syncthreads();
        mma_chunk(a_s, b_s, tx, ty, acc);
        __syncthreads();
    }
    float invL = g_scal[3], lam = g_scal[4];
    float bw0 = smw[20], bw1 = smw[21];
#pragma unroll
    for (int i = 0; i < 8; ++i) {
        size_t off = (size_t)(m0 + ty * 8 + i) * H_DIM + n0 + tx * 8;
        float zl[8], zpl[8], ul[8], zo[8], zp2[8];
        *(float4*)&zl[0]  = *(const float4*)&z_in[off];
        *(float4*)&zl[4]  = *(const float4*)&z_in[off + 4];
        *(float4*)&zpl[0] = *(const float4*)&zp_in[off];
        *(float4*)&zpl[4] = *(const float4*)&zp_in[off + 4];
        *(float4*)&ul[0]  = *(const float4*)&g_u[off];
        *(float4*)&ul[4]  = *(const float4*)&g_u[off + 4];
#pragma unroll
        for (int j = 0; j < 8; ++j) {
            float zaux = zl[j] + mom * (zl[j] - zpl[j]);
            float zg   = zaux - (acc[i][j] - ul[j]) * invL;
            float zop  = act_mix(zg, smw, lam);
            zo[j]  = zop;
            zp2[j] = bw0 * zl[j] + bw1 * zop;
        }
        *(float4*)&z_out[off]     = *(float4*)&zo[0];
        *(float4*)&z_out[off + 4] = *(float4*)&zo[4];
        if (write_zp) {
            *(float4*)&zp_out[off]     = *(float4*)&zp2[0];
            *(float4*)&zp_out[off + 4] = *(float4*)&zp2[4];
        }
    }
}

// ---------------- host orchestration (graph-capturable: kernel launches only) ----------------
extern "C" void kernel_launch(void* const* d_in, const int* in_sizes, int n_in,
                              void* d_out, int out_size) {
    const float* x     = (const float*)d_in[0];
    const float* W     = (const float*)d_in[1];
    const float* alpha = (const float*)d_in[2];
    const float* lbeta = (const float*)d_in[3];
    float* out = (float*)d_out;
    int T = in_sizes[2] / NOPS;
    if (T < 1) T = 1;
    if (T > 16) T = 16;

    dim3 thr(256);

    // Spectral norm: A = WW^T, then 12 trace-normalized squarings -> L
    k_gemm_wwT<<<dim3(4, 4), thr>>>(W);
    int cur = 0;
    for (int j = 0; j < PWRK; ++j) {
        k_trace<<<1, 512>>>(cur, (j == 0) ? 1 : 0, 0);
        k_gemm_square<<<dim3(4, 4), thr>>>(cur);
        cur ^= 1;
    }
    k_trace<<<1, 512>>>(cur, 0, 1);

    // One-time precomputes
    k_gemm_C<<<dim3(8, 8), thr>>>(W);
    k_gemm_u<<<dim3(8, 32), thr>>>(x, W);
    k_weights<<<1, 32>>>(alpha, lbeta, T);

    // Iteration 0 (z = zprev = 0): elementwise only
    k_iter0<<<(B_DIM * H_DIM) / (256 * 4), 256>>>((T == 1) ? out : nullptr);

    // Iterations 1..T-1: fused GEMM + epilogue, ping-pong buffers; last writes d_out
    for (int i = 1; i < T; ++i) {
        float mom = (float)((double)i / (double)(i + 3));
        int inSel  = (i + 1) & 1;
        int outSel = i & 1;
        int last = (i == T - 1);
        k_gemm_iter<<<dim3(8, 32), thr>>>(inSel, outSel, last ? out : nullptr,
                                          i, mom, last ? 0 : 1);
    }
}